// round 7
// baseline (speedup 1.0000x reference)
#include <cuda_runtime.h>
#include <cstdint>

// TaylorMap via classic mma.sync (sm_103 has NO tcgen05 in this build env):
//   out = x + P(x) @ W,  P:[B,969] monomials in reference order, f16.
//   x:[262144,16] f32, W:[969,16] f32, out:[262144,16] f32.
//
// Feature order: k=0:1; k=1..16: x_i; k=17..152: x_a x_b (a>=b);
//   k=153..968: x_ii x_a x_b (ii>=a>=b), k = 153 + C(ii+2,3) + a(a+1)/2 + b.
// K padded to 992 = 62 mma k-steps (m16n8k16).
//
// Per warp: one 32-row tile. Lane l generates row l's monomials (f32),
// packs k-pairs to f16x2, stages through smem (XOR-swizzled, conflict-free
// both sides), then the same warp runs mma.sync m16n8k16 f16/f32:
// 2 row-subtiles x 2 n-tiles = 4 mma per k-step, D in 16 f32 regs.
// B fragments prebuilt in smem in per-lane fragment order (1 LDS.128/step).
// Epilogue adds x in f32 (x path stays exact; only P@W sees f16).

typedef unsigned int u32;
typedef unsigned long long u64;

#define NF 16
#define KTOT 992
#define NSTEP 62                    // k16 steps
#define BLOCK 256
#define GRID 296                    // 2 CTAs/SM
#define NBATCH 262144
#define NTILES (NBATCH / 32)        // 8192 tiles of 32 rows
#define BFRAG_BYTES (NSTEP * 32 * 16)     // 31744
#define PSM_OFF BFRAG_BYTES
#define PSM_PER_WARP 8192           // two 4KB chunk buffers
#define SMEM_TOTAL (BFRAG_BYTES + 8 * PSM_PER_WARP)   // 97280

__device__ unsigned int g_ticket;
__global__ void reset_ticket_kernel() { g_ticket = 0u; }

__device__ __forceinline__ u32 smem_u32(const void* p) {
    u32 a;
    asm("{ .reg .u64 t; cvta.to.shared.u64 t, %1; cvt.u32.u64 %0, t; }"
        : "=r"(a) : "l"(p));
    return a;
}
__device__ __forceinline__ u32 packf16(float hi, float lo) {
    u32 r; asm("cvt.rn.f16x2.f32 %0, %1, %2;" : "=r"(r) : "f"(hi), "f"(lo));
    return r;
}
__device__ __forceinline__ u32 lds32(u32 addr) {
    u32 v; asm volatile("ld.shared.b32 %0, [%1];" : "=r"(v) : "r"(addr));
    return v;
}
__device__ __forceinline__ void sts32(u32 addr, u32 v) {
    asm volatile("st.shared.b32 [%0], %1;" :: "r"(addr), "r"(v));
}
__device__ __forceinline__ void mma16816(float& d0, float& d1, float& d2, float& d3,
                                         u32 a0, u32 a1, u32 a2, u32 a3,
                                         u32 b0, u32 b1) {
    asm volatile("mma.sync.aligned.m16n8k16.row.col.f32.f16.f16.f32 "
                 "{%0,%1,%2,%3}, {%4,%5,%6,%7}, {%8,%9}, {%0,%1,%2,%3};"
                 : "+f"(d0), "+f"(d1), "+f"(d2), "+f"(d3)
                 : "r"(a0), "r"(a1), "r"(a2), "r"(a3), "r"(b0), "r"(b1));
}

__global__ void __launch_bounds__(BLOCK, 2)
taylor_mma(const float* __restrict__ x, const float* __restrict__ W,
           float* __restrict__ out)
{
    extern __shared__ unsigned char smem[];
    const u32 sbase = smem_u32(smem);
    const int tid = threadIdx.x;
    const int warp = tid >> 5;
    const int lane = tid & 31;
    const int g = lane >> 2;          // fragment row group 0..7
    const int t = lane & 3;           // fragment thread-in-group 0..3

    // ---- build B fragments once: Bfrag[s][lane] = {b0n0,b1n0,b0n1,b1n1} ----
    // b0n0 = f16x2{ W[16s+2t][g](lo),   W[16s+2t+1][g](hi) }
    // b1n0 = f16x2{ W[16s+2t+8][g](lo), W[16s+2t+9][g](hi) }; n1: col g+8.
#pragma unroll 1
    for (int e = tid; e < NSTEP * 32; e += BLOCK) {
        int s = e >> 5, l = e & 31;
        int lg = l >> 2, lt = l & 3;
        int k1 = 16 * s + 2 * lt;
#define WGET(K, C) (((K) < 969) ? W[(K) * NF + (C)] : 0.0f)
        uint4 v;
        v.x = packf16(WGET(k1 + 1, lg),     WGET(k1, lg));
        v.y = packf16(WGET(k1 + 9, lg),     WGET(k1 + 8, lg));
        v.z = packf16(WGET(k1 + 1, lg + 8), WGET(k1, lg + 8));
        v.w = packf16(WGET(k1 + 9, lg + 8), WGET(k1 + 8, lg + 8));
#undef WGET
        *reinterpret_cast<uint4*>(smem + e * 16) = v;
    }
    __syncthreads();

    // ---- per-lane smem address bases (all later offsets are immediates) ----
    const u32 psmw = sbase + PSM_OFF + warp * PSM_PER_WARP;
    // producer: row = lane; col(lp) = cp0 ^ (lp&3), cp0 = 4*(lane&7)+(lane>>3)
    const u32 cp0 = ((lane & 7) << 2) + (lane >> 3);
    u32 rst[4];
#pragma unroll
    for (int j = 0; j < 4; j++) rst[j] = psmw + ((cp0 ^ j) << 2);
    // consumer: a-reg for row-octet o at col ((4g+o)^t); kpair low bits add t*128
    u32 ao[4];
#pragma unroll
    for (int o = 0; o < 4; o++)
        ao[o] = psmw + (u32)(t * 128) + ((((g << 2) + o) ^ t) << 2);
    const u32 rb = sbase + lane * 16;   // B fragment base (this lane)

    for (;;) {
        u32 tk;
        if (lane == 0) tk = atomicAdd(&g_ticket, 1u);
        tk = __shfl_sync(0xffffffffu, tk, 0);
        if (tk >= NTILES) break;

        const long long base = (long long)tk * 32;

        // ---- load this lane's x row ----
        const float4* xv = reinterpret_cast<const float4*>(x + (base + lane) * NF);
        float4 v0 = xv[0], v1 = xv[1], v2 = xv[2], v3 = xv[3];
        float xs[NF] = { v0.x, v0.y, v0.z, v0.w,  v1.x, v1.y, v1.z, v1.w,
                         v2.x, v2.y, v2.z, v2.w,  v3.x, v3.y, v3.z, v3.w };

        float d0[4] = {0, 0, 0, 0};   // su0,nt0
        float d1[4] = {0, 0, 0, 0};   // su0,nt1
        float d2[4] = {0, 0, 0, 0};   // su1,nt0
        float d3[4] = {0, 0, 0, 0};   // su1,nt1
        float m_pend = 0.0f;

        // Consume NS k-steps of chunk CH (4 steps = 64 k per full chunk).
#define CONSUME(CH, NS) do {                                                   \
        __syncwarp();                                                          \
        _Pragma("unroll")                                                      \
        for (int _sl = 0; _sl < (NS); _sl++) {                                 \
            const u32 IMM = (u32)((((CH) & 1) * 4096) + _sl * 1024);           \
            u32 b0, b1, b2, b3;                                                \
            asm volatile("ld.shared.v4.b32 {%0,%1,%2,%3}, [%4];"               \
                : "=r"(b0), "=r"(b1), "=r"(b2), "=r"(b3)                       \
                : "r"(rb + (u32)(((CH) * 4 + _sl) * 512)));                    \
            u32 a0 = lds32(ao[0] + IMM);                                       \
            u32 a1 = lds32(ao[1] + IMM);                                       \
            u32 a2 = lds32(ao[0] + IMM + 512);                                 \
            u32 a3 = lds32(ao[1] + IMM + 512);                                 \
            mma16816(d0[0], d0[1], d0[2], d0[3], a0, a1, a2, a3, b0, b1);      \
            mma16816(d1[0], d1[1], d1[2], d1[3], a0, a1, a2, a3, b2, b3);      \
            a0 = lds32(ao[2] + IMM);                                           \
            a1 = lds32(ao[3] + IMM);                                           \
            a2 = lds32(ao[2] + IMM + 512);                                     \
            a3 = lds32(ao[3] + IMM + 512);                                     \
            mma16816(d2[0], d2[1], d2[2], d2[3], a0, a1, a2, a3, b0, b1);      \
            mma16816(d3[0], d3[1], d3[2], d3[3], a0, a1, a2, a3, b2, b3);      \
        }                                                                      \
    } while (0)

        // Emit monomial k (ascending); pack pairs; STS; consume at chunk ends.
#define EMITK(KK, V) do {                                                      \
        if (((KK) & 1) == 0) { m_pend = (V); }                                 \
        else {                                                                 \
            u32 _h = packf16((V), m_pend);                                     \
            sts32(rst[((KK) >> 1) & 3]                                         \
                  + (u32)(((((KK) >> 1) >> 5) & 1) * 4096                      \
                          + (((KK) >> 1) & 31) * 128), _h);                    \
            if (((KK) & 63) == 63) CONSUME((KK) >> 6, 4);                      \
            else if ((KK) == 991) CONSUME(15, 2);                              \
        }                                                                      \
    } while (0)

        EMITK(0, 1.0f);
#pragma unroll
        for (int i = 0; i < NF; i++) EMITK(1 + i, xs[i]);
#pragma unroll
        for (int a = 0; a < NF; a++)
#pragma unroll
            for (int b = 0; b <= a; b++)
                EMITK(17 + (a * (a + 1)) / 2 + b, xs[a] * xs[b]);
#pragma unroll
        for (int ii = 0; ii < NF; ii++)
#pragma unroll
            for (int a = 0; a <= ii; a++) {
                float tprod = xs[ii] * xs[a];
                const int r0 = 153 + (ii * (ii + 1) * (ii + 2)) / 6
                             + (a * (a + 1)) / 2;
#pragma unroll
                for (int b = 0; b <= a; b++) EMITK(r0 + b, tprod * xs[b]);
            }
#pragma unroll
        for (int k = 969; k < KTOT; k++) EMITK(k, 0.0f);
#undef EMITK
#undef CONSUME

        // ---- epilogue: out = x + D (f32; x path exact) ----
#define EPI(DARR, SU, NT) do {                                                 \
        long long rlo = base + (SU) * 16 + g;                                  \
        int c = (NT) * 8 + 2 * t;                                              \
        const float2 xlo = *reinterpret_cast<const float2*>(x + rlo * NF + c); \
        float2 olo; olo.x = xlo.x + (DARR)[0]; olo.y = xlo.y + (DARR)[1];      \
        *reinterpret_cast<float2*>(out + rlo * NF + c) = olo;                  \
        const float2 xhi = *reinterpret_cast<const float2*>(x + (rlo + 8) * NF + c); \
        float2 ohi; ohi.x = xhi.x + (DARR)[2]; ohi.y = xhi.y + (DARR)[3];      \
        *reinterpret_cast<float2*>(out + (rlo + 8) * NF + c) = ohi;            \
    } while (0)
        EPI(d0, 0, 0);
        EPI(d1, 0, 1);
        EPI(d2, 1, 0);
        EPI(d3, 1, 1);
#undef EPI
    }
}

extern "C" void kernel_launch(void* const* d_in, const int* in_sizes, int n_in,
                              void* d_out, int out_size)
{
    const float* x = (const float*)d_in[0];   // [262144, 16]
    const float* W = (const float*)d_in[1];   // [969, 16]
    float* out = (float*)d_out;

    cudaFuncSetAttribute(taylor_mma,
                         cudaFuncAttributeMaxDynamicSharedMemorySize,
                         SMEM_TOTAL);

    reset_ticket_kernel<<<1, 1>>>();
    taylor_mma<<<GRID, BLOCK, SMEM_TOTAL>>>(x, W, out);
}

// round 8
// speedup vs baseline: 1.4704x; 1.4704x over previous
#include <cuda_runtime.h>
#include <cstdint>

// TaylorMap via classic mma.sync m16n8k16 f16/f32 (sm_103: no tcgen05).
//   out = x + P(x) @ W,  P:[B,969->992] monomials (reference order) in f16.
// R8 = R7's validated layouts (swizzle / fragments / epilogue, rel_err 1.1e-4)
// with the serialization fixed: consume k-steps are interleaved into the NEXT
// chunk's generation stream (one mma step per 16 generated k), so volatile-asm
// program order itself forms the software pipeline. Double-buffered P smem.

typedef unsigned int u32;
typedef unsigned long long u64;

#define NF 16
#define KTOT 992
#define NSTEP 62
#define BLOCK 256
#define GRID 296                    // 2 CTAs/SM
#define NBATCH 262144
#define NTILES (NBATCH / 32)        // 8192 tiles of 32 rows
#define BFRAG_BYTES (NSTEP * 32 * 16)     // 31744
#define PSM_OFF BFRAG_BYTES
#define PSM_PER_WARP 8192           // two 4KB chunk buffers
#define SMEM_TOTAL (BFRAG_BYTES + 8 * PSM_PER_WARP)   // 97280

__device__ unsigned int g_ticket;
__global__ void reset_ticket_kernel() { g_ticket = 0u; }

__device__ __forceinline__ u32 smem_u32(const void* p) {
    u32 a;
    asm("{ .reg .u64 t; cvta.to.shared.u64 t, %1; cvt.u32.u64 %0, t; }"
        : "=r"(a) : "l"(p));
    return a;
}
__device__ __forceinline__ u32 packf16(float hi, float lo) {
    u32 r; asm("cvt.rn.f16x2.f32 %0, %1, %2;" : "=r"(r) : "f"(hi), "f"(lo));
    return r;
}
__device__ __forceinline__ u32 lds32(u32 addr) {
    u32 v; asm volatile("ld.shared.b32 %0, [%1];" : "=r"(v) : "r"(addr));
    return v;
}
__device__ __forceinline__ void sts32(u32 addr, u32 v) {
    asm volatile("st.shared.b32 [%0], %1;" :: "r"(addr), "r"(v));
}

__global__ void __launch_bounds__(BLOCK, 2)
taylor_mma(const float* __restrict__ x, const float* __restrict__ W,
           float* __restrict__ out)
{
    extern __shared__ unsigned char smem[];
    const u32 sbase = smem_u32(smem);
    const int tid = threadIdx.x;
    const int warp = tid >> 5;
    const int lane = tid & 31;
    const int g = lane >> 2;          // fragment row group 0..7
    const int t = lane & 3;           // thread-in-group 0..3

    // ---- build B fragments once (same as R7, validated) ----
#pragma unroll 1
    for (int e = tid; e < NSTEP * 32; e += BLOCK) {
        int s = e >> 5, l = e & 31;
        int lg = l >> 2, lt = l & 3;
        int k1 = 16 * s + 2 * lt;
#define WGET(K, C) (((K) < 969) ? W[(K) * NF + (C)] : 0.0f)
        uint4 v;
        v.x = packf16(WGET(k1 + 1, lg),     WGET(k1, lg));
        v.y = packf16(WGET(k1 + 9, lg),     WGET(k1 + 8, lg));
        v.z = packf16(WGET(k1 + 1, lg + 8), WGET(k1, lg + 8));
        v.w = packf16(WGET(k1 + 9, lg + 8), WGET(k1 + 8, lg + 8));
#undef WGET
        *reinterpret_cast<uint4*>(smem + e * 16) = v;
    }
    __syncthreads();

    // ---- per-lane smem bases (scalarized; later offsets are immediates) ----
    const u32 psmw = sbase + PSM_OFF + warp * PSM_PER_WARP;
    const u32 cp0 = ((lane & 7) << 2) + (lane >> 3);
    const u32 rst0 = psmw + ((cp0 ^ 0) << 2);
    const u32 rst1 = psmw + ((cp0 ^ 1) << 2);
    const u32 rst2 = psmw + ((cp0 ^ 2) << 2);
    const u32 rst3 = psmw + ((cp0 ^ 3) << 2);
    const u32 ao0 = psmw + (u32)(t * 128) + ((((g << 2) + 0) ^ t) << 2);
    const u32 ao1 = psmw + (u32)(t * 128) + ((((g << 2) + 1) ^ t) << 2);
    const u32 ao2 = psmw + (u32)(t * 128) + ((((g << 2) + 2) ^ t) << 2);
    const u32 ao3 = psmw + (u32)(t * 128) + ((((g << 2) + 3) ^ t) << 2);
    const u32 rb = sbase + lane * 16;

    for (;;) {
        u32 tk;
        if (lane == 0) tk = atomicAdd(&g_ticket, 1u);
        tk = __shfl_sync(0xffffffffu, tk, 0);
        if (tk >= NTILES) break;

        const long long base = (long long)tk * 32;

        const float4* xv = reinterpret_cast<const float4*>(x + (base + lane) * NF);
        float4 v0 = xv[0], v1 = xv[1], v2 = xv[2], v3 = xv[3];
        float xs[NF] = { v0.x, v0.y, v0.z, v0.w,  v1.x, v1.y, v1.z, v1.w,
                         v2.x, v2.y, v2.z, v2.w,  v3.x, v3.y, v3.z, v3.w };

        float d00 = 0, d01 = 0, d02 = 0, d03 = 0;   // su0,nt0
        float d10 = 0, d11 = 0, d12 = 0, d13 = 0;   // su0,nt1
        float d20 = 0, d21 = 0, d22 = 0, d23 = 0;   // su1,nt0
        float d30 = 0, d31 = 0, d32 = 0, d33 = 0;   // su1,nt1
        float m_pend = 0.0f;

        // One consume k-step: CH = chunk (buffer parity CH&1), S = step 0..3.
#define CSTEP(CH, S) do {                                                      \
        u32 b0, b1, b2, b3;                                                    \
        asm volatile("ld.shared.v4.b32 {%0,%1,%2,%3}, [%4];"                   \
            : "=r"(b0), "=r"(b1), "=r"(b2), "=r"(b3)                           \
            : "r"(rb + (u32)((4 * (CH) + (S)) * 512)));                        \
        const u32 IMM = (u32)((((CH) & 1) * 4096) + (S) * 1024);               \
        u32 a0 = lds32(ao0 + IMM);                                             \
        u32 a1 = lds32(ao1 + IMM);                                             \
        u32 a2 = lds32(ao0 + IMM + 512);                                       \
        u32 a3 = lds32(ao1 + IMM + 512);                                       \
        asm volatile("mma.sync.aligned.m16n8k16.row.col.f32.f16.f16.f32 "      \
            "{%0,%1,%2,%3}, {%4,%5,%6,%7}, {%8,%9}, {%0,%1,%2,%3};"            \
            : "+f"(d00), "+f"(d01), "+f"(d02), "+f"(d03)                       \
            : "r"(a0), "r"(a1), "r"(a2), "r"(a3), "r"(b0), "r"(b1));           \
        asm volatile("mma.sync.aligned.m16n8k16.row.col.f32.f16.f16.f32 "      \
            "{%0,%1,%2,%3}, {%4,%5,%6,%7}, {%8,%9}, {%0,%1,%2,%3};"            \
            : "+f"(d10), "+f"(d11), "+f"(d12), "+f"(d13)                       \
            : "r"(a0), "r"(a1), "r"(a2), "r"(a3), "r"(b2), "r"(b3));           \
        u32 a4 = lds32(ao2 + IMM);                                             \
        u32 a5 = lds32(ao3 + IMM);                                             \
        u32 a6 = lds32(ao2 + IMM + 512);                                       \
        u32 a7 = lds32(ao3 + IMM + 512);                                       \
        asm volatile("mma.sync.aligned.m16n8k16.row.col.f32.f16.f16.f32 "      \
            "{%0,%1,%2,%3}, {%4,%5,%6,%7}, {%8,%9}, {%0,%1,%2,%3};"            \
            : "+f"(d20), "+f"(d21), "+f"(d22), "+f"(d23)                       \
            : "r"(a4), "r"(a5), "r"(a6), "r"(a7), "r"(b0), "r"(b1));           \
        asm volatile("mma.sync.aligned.m16n8k16.row.col.f32.f16.f16.f32 "      \
            "{%0,%1,%2,%3}, {%4,%5,%6,%7}, {%8,%9}, {%0,%1,%2,%3};"            \
            : "+f"(d30), "+f"(d31), "+f"(d32), "+f"(d33)                       \
            : "r"(a4), "r"(a5), "r"(a6), "r"(a7), "r"(b2), "r"(b3));           \
    } while (0)

#define RSTSEL(J) ((J) == 0 ? rst0 : (J) == 1 ? rst1 : (J) == 2 ? rst2 : rst3)

        // Emit monomial k; store f16 pairs; interleave one consume step of the
        // PREVIOUS chunk every 16 k; syncwarp at 64-k chunk boundaries.
#define EMITK(KK, V) do {                                                      \
        if (((KK) & 1) == 0) { m_pend = (V); }                                 \
        else {                                                                 \
            u32 _h = packf16((V), m_pend);                                     \
            const int _kp = (KK) >> 1;                                         \
            sts32(RSTSEL(_kp & 3)                                              \
                  + (u32)((((_kp >> 5) & 1) * 4096) + (_kp & 31) * 128), _h);  \
            if ((KK) >= 79 && ((KK) & 15) == 15)                               \
                CSTEP(((KK) >> 6) - 1, ((KK) >> 4) & 3);                       \
            if (((KK) & 63) == 63) __syncwarp();                               \
        }                                                                      \
    } while (0)

        EMITK(0, 1.0f);
#pragma unroll
        for (int i = 0; i < NF; i++) EMITK(1 + i, xs[i]);
#pragma unroll
        for (int a = 0; a < NF; a++)
#pragma unroll
            for (int b = 0; b <= a; b++)
                EMITK(17 + (a * (a + 1)) / 2 + b, xs[a] * xs[b]);
#pragma unroll
        for (int ii = 0; ii < NF; ii++)
#pragma unroll
            for (int a = 0; a <= ii; a++) {
                float tprod = xs[ii] * xs[a];
                const int r0 = 153 + (ii * (ii + 1) * (ii + 2)) / 6
                             + (a * (a + 1)) / 2;
#pragma unroll
                for (int b = 0; b <= a; b++) EMITK(r0 + b, tprod * xs[b]);
            }
#pragma unroll
        for (int k = 969; k < KTOT; k++) EMITK(k, 0.0f);
#undef EMITK

        // Tail: chunk 15 only spans k 960..991 (fires steps (14,0),(14,1)).
        CSTEP(14, 2);
        CSTEP(14, 3);
        CSTEP(15, 0);   // buf1 writes ordered by the syncwarp at k=991
        CSTEP(15, 1);
#undef CSTEP
#undef RSTSEL

        // ---- epilogue: out = x + D (f32; x path exact) ----
#define EPI(D0, D1, D2, D3, SU, NT) do {                                       \
        long long rlo = base + (SU) * 16 + g;                                  \
        int c = (NT) * 8 + 2 * t;                                              \
        const float2 xlo = *reinterpret_cast<const float2*>(x + rlo * NF + c); \
        float2 olo; olo.x = xlo.x + (D0); olo.y = xlo.y + (D1);                \
        *reinterpret_cast<float2*>(out + rlo * NF + c) = olo;                  \
        const float2 xhi = *reinterpret_cast<const float2*>(x + (rlo + 8) * NF + c); \
        float2 ohi; ohi.x = xhi.x + (D2); ohi.y = xhi.y + (D3);                \
        *reinterpret_cast<float2*>(out + (rlo + 8) * NF + c) = ohi;            \
    } while (0)
        EPI(d00, d01, d02, d03, 0, 0);
        EPI(d10, d11, d12, d13, 0, 1);
        EPI(d20, d21, d22, d23, 1, 0);
        EPI(d30, d31, d32, d33, 1, 1);
#undef EPI
    }
}

extern "C" void kernel_launch(void* const* d_in, const int* in_sizes, int n_in,
                              void* d_out, int out_size)
{
    const float* x = (const float*)d_in[0];   // [262144, 16]
    const float* W = (const float*)d_in[1];   // [969, 16]
    float* out = (float*)d_out;

    cudaFuncSetAttribute(taylor_mma,
                         cudaFuncAttributeMaxDynamicSharedMemorySize,
                         SMEM_TOTAL);

    reset_ticket_kernel<<<1, 1>>>();
    taylor_mma<<<GRID, BLOCK, SMEM_TOTAL>>>(x, W, out);
}